// round 10
// baseline (speedup 1.0000x reference)
#include <cuda_runtime.h>
#include <cuda_bf16.h>
#include <cstdint>

// Problem constants (from reference_code)
constexpr int NNB     = 16;        // N_NEIGH
constexpr int NFEAT   = 32;        // N_FEAT
constexpr int ROW     = 3 + 3 * NFEAT;   // 99 features per pair
constexpr int PAIRS   = NNB * NNB - NNB; // 240 off-diagonal pairs
constexpr int PER_C   = PAIRS * ROW;     // 23760 floats per center

// CTA-wide slab staging: 80 pairs per slab (8 warps x 10 pairs), 3 slabs/center
constexpr int SLAB_PAIRS  = 80;
constexpr int NSLABS      = PAIRS / SLAB_PAIRS;     // 3
constexpr int SLAB_FLOATS = SLAB_PAIRS * ROW;       // 7920
constexpr int SLAB_BYTES  = SLAB_FLOATS * 4;        // 31680 (16B multiple)
constexpr int PPW         = SLAB_PAIRS / 8;         // 10 pairs per warp per slab

constexpr int CPC = 4;   // adjacent centers per CTA (contiguous 380KB output)

__global__ void __launch_bounds__(256)
ang_desc_kernel(const float* __restrict__ atoms_xyz,   // [N_ATOMS,3]
                const float* __restrict__ embed,       // [N_TYPES,32]
                const float* __restrict__ dist,        // [C,16]
                const int*   __restrict__ types,       // [N_ATOMS]
                const int*   __restrict__ i_idx,       // [C]
                const int*   __restrict__ j_idx,       // [C,16]
                float*       __restrict__ out,         // [C,240,99]
                float*       __restrict__ centers_out, // [C]
                int C)
{
    const int t = threadIdx.x;

    // Double-buffered DERIVED tables (consumed by slab builds)
    __shared__ float s_d[2][NNB];
    __shared__ float s_embi[2][NFEAT];
    __shared__ float s_embj[2][NNB * NFEAT];
    __shared__ float s_norm[2][NNB * NNB];
    // Single-set INTERMEDIATES (only bridge stage A -> stage B of prefetch)
    __shared__ float s_inv[NNB], s_x[NNB], s_y[NNB], s_z[NNB];
    __shared__ int   s_tj[NNB];
    // double-buffered CTA-wide slab: 2 x 31680 B
    __shared__ __align__(16) float s_stage[2][SLAB_FLOATS];

    const int warp = t >> 5;
    const int lane = t & 31;
    const int rot  = (lane - 3) & 31;
    const bool l0 = (lane == 0), l1 = (lane == 1), l2 = (lane == 2);
    const bool llt3 = (lane < 3);

    uint64_t policy;
    asm volatile("createpolicy.fractional.L2::evict_first.b64 %0, 1.0;"
                 : "=l"(policy));

    const int c0 = blockIdx.x * CPC;

    // ================= first-center prologue (only exposed one) =============
    if (t < NNB) {
        float d = dist[c0 * NNB + t];
        int   a = j_idx[c0 * NNB + t];
        s_d[0][t] = d;
        s_inv[t]  = 1.0f / d;
        s_x[t]  = atoms_xyz[a * 3 + 0];
        s_y[t]  = atoms_xyz[a * 3 + 1];
        s_z[t]  = atoms_xyz[a * 3 + 2];
        s_tj[t] = types[a];
    } else if (t >= 32 && t < 64) {
        int ln = t - 32;
        int ai = i_idx[c0];           // broadcast
        int ti = types[ai];           // broadcast
        s_embi[0][ln] = embed[ti * NFEAT + ln];
        if (ln == 0) centers_out[c0] = (float)ai;
    }
    __syncthreads();
    {
        #pragma unroll
        for (int idx = t; idx < NNB * NFEAT; idx += 256) {
            int nb = idx >> 5, f = idx & 31;
            s_embj[0][idx] = embed[s_tj[nb] * NFEAT + f] * s_inv[nb];
        }
        int j = t >> 4, k = t & 15;
        float dx = s_x[j] - s_x[k];
        float dy = s_y[j] - s_y[k];
        float dz = s_z[j] - s_z[k];
        float djk = sqrtf(dx * dx + dy * dy + dz * dz);
        float dj = s_d[0][j], dk = s_d[0][k];
        float mx = fmaxf(dj, dk), mn = fminf(dj, dk);
        s_norm[0][t] = (djk - mx + mn) / (2.0f * mn);
    }
    __syncthreads();

    int it = 0;  // slab counter: s_stage parity carries across centers

    #pragma unroll 1
    for (int cc = 0; cc < CPC; ++cc) {
        const int c = c0 + cc;
        if (c >= C) break;
        const int p  = cc & 1;              // current table set
        const int pn = p ^ 1;               // next-center table set
        const int n  = c + 1;               // prefetch target
        const bool pf = (cc + 1 < CPC) && (n < C);

        const float embi_a = s_embi[p][rot];
        const float embi_b = s_embi[p][(29 + lane) < NFEAT ? (29 + lane) : 0];
        char* gbase = (char*)(out + (size_t)c * PER_C);

        for (int s = 0; s < NSLABS; ++s, ++it) {
            float* buf = s_stage[it & 1];

            #pragma unroll
            for (int r = 0; r < PPW; ++r) {
                const int rp = warp * PPW + r;       // row within slab
                const int pp = s * SLAB_PAIRS + rp;  // global pair index
                const int q  = pp + (pp >> 4) + 1;   // skip-diagonal flat index
                const int j  = q >> 4;
                const int k  = q & 15;

                const float dj  = s_d[p][j];
                const float dk  = s_d[p][k];
                const float njk = s_norm[p][q];
                const float ejv = s_embj[p][j * NFEAT + rot];
                const float ekv = s_embj[p][k * NFEAT + rot];

                float v0 = embi_a;               // [dj, dk, njk, emb_i[0..28]]
                if (l2) v0 = njk;
                if (l1) v0 = dk;
                if (l0) v0 = dj;
                float v1 = llt3 ? embi_b : ejv;  // [emb_i[29..31], e_j[0..28]]
                float v2 = llt3 ? ejv    : ekv;  // [e_j[29..31],  e_k[0..28]]

                float* rb = buf + rp * ROW;
                rb[lane]      = v0;
                rb[32 + lane] = v1;
                rb[64 + lane] = v2;
                if (llt3) rb[96 + lane] = ekv;   // e_k[29..31]
            }

            // ---- prefetch next center, hidden under slab builds ----
            if (s == 0 && pf) {
                // stage A: raw gathers (latency hidden behind build+drain)
                if (t < NNB) {
                    float d = dist[n * NNB + t];
                    int   a = j_idx[n * NNB + t];
                    s_d[pn][t] = d;
                    s_inv[t]  = 1.0f / d;
                    s_x[t]  = atoms_xyz[a * 3 + 0];
                    s_y[t]  = atoms_xyz[a * 3 + 1];
                    s_z[t]  = atoms_xyz[a * 3 + 2];
                    s_tj[t] = types[a];
                } else if (t >= 32 && t < 64) {
                    int ln = t - 32;
                    int ai = i_idx[n];           // broadcast
                    int ti = types[ai];          // broadcast
                    s_embi[pn][ln] = embed[ti * NFEAT + ln];
                    if (ln == 0) centers_out[n] = (float)ai;
                }
            } else if (s == 1 && pf) {
                // stage B: derived tables (ordered by slab-0's syncs)
                #pragma unroll
                for (int idx = t; idx < NNB * NFEAT; idx += 256) {
                    int nb = idx >> 5, f = idx & 31;
                    s_embj[pn][idx] = embed[s_tj[nb] * NFEAT + f] * s_inv[nb];
                }
                int j = t >> 4, k = t & 15;
                float dx = s_x[j] - s_x[k];
                float dy = s_y[j] - s_y[k];
                float dz = s_z[j] - s_z[k];
                float djk = sqrtf(dx * dx + dy * dy + dz * dz);
                float dj = s_d[pn][j], dk = s_d[pn][k];
                float mx = fmaxf(dj, dk), mn = fminf(dj, dk);
                s_norm[pn][t] = (djk - mx + mn) / (2.0f * mn);
            }

            __syncthreads();   // slab built (and stage A/B published)
            if (t == 0) {
                asm volatile("fence.proxy.async.shared::cta;" ::: "memory");
                uint32_t saddr = (uint32_t)__cvta_generic_to_shared(buf);
                asm volatile(
                    "cp.async.bulk.global.shared::cta.bulk_group.L2::cache_hint"
                    " [%0], [%1], %2, %3;"
                    :: "l"(gbase + (size_t)s * SLAB_BYTES), "r"(saddr),
                       "n"(SLAB_BYTES), "l"(policy)
                    : "memory");
                asm volatile("cp.async.bulk.commit_group;" ::: "memory");
                // <=1 older bulk in flight: buffer reused next iteration
                // (committed 2 slabs ago) is guaranteed drained
                asm volatile("cp.async.bulk.wait_group 1;" ::: "memory");
            }
            __syncthreads();
        }
        // no drain at center boundary — tables for c+1 already built
    }

    // SMEM handed to next CTA on this SM: drain fully before exit
    if (t == 0)
        asm volatile("cp.async.bulk.wait_group 0;" ::: "memory");
}

extern "C" void kernel_launch(void* const* d_in, const int* in_sizes, int n_in,
                              void* d_out, int out_size)
{
    const float* atoms_xyz = (const float*)d_in[0];
    const float* embed     = (const float*)d_in[1];
    const float* dist      = (const float*)d_in[2];
    const int*   types     = (const int*)  d_in[3];
    const int*   i_idx     = (const int*)  d_in[4];
    const int*   j_idx     = (const int*)  d_in[5];

    const int C = in_sizes[4];                 // number of centers
    float* out = (float*)d_out;
    float* centers_out = out + (size_t)C * PER_C;

    int grid = (C + CPC - 1) / CPC;            // 4 adjacent centers per CTA

    ang_desc_kernel<<<grid, 256>>>(atoms_xyz, embed, dist, types,
                                   i_idx, j_idx, out, centers_out, C);
}

// round 11
// speedup vs baseline: 1.0584x; 1.0584x over previous
#include <cuda_runtime.h>
#include <cuda_bf16.h>
#include <cstdint>

// Problem constants (from reference_code)
constexpr int NNB     = 16;        // N_NEIGH
constexpr int NFEAT   = 32;        // N_FEAT
constexpr int ROW     = 3 + 3 * NFEAT;   // 99 features per pair
constexpr int PAIRS   = NNB * NNB - NNB; // 240 off-diagonal pairs
constexpr int PER_C   = PAIRS * ROW;     // 23760 floats per center

// CTA-wide slab staging: 80 pairs per slab (8 warps x 10 pairs), 3 slabs/center
constexpr int SLAB_PAIRS  = 80;
constexpr int NSLABS      = PAIRS / SLAB_PAIRS;     // 3
constexpr int SLAB_FLOATS = SLAB_PAIRS * ROW;       // 7920
constexpr int SLAB_BYTES  = SLAB_FLOATS * 4;        // 31680 (16B multiple)
constexpr int PPW         = SLAB_PAIRS / 8;         // 10 pairs per warp per slab

constexpr int CPC = 2;   // adjacent centers per CTA (contiguous 190KB output)

__global__ void __launch_bounds__(256)
ang_desc_kernel(const float* __restrict__ atoms_xyz,   // [N_ATOMS,3]
                const float* __restrict__ embed,       // [N_TYPES,32]
                const float* __restrict__ dist,        // [C,16]
                const int*   __restrict__ types,       // [N_ATOMS]
                const int*   __restrict__ i_idx,       // [C]
                const int*   __restrict__ j_idx,       // [C,16]
                float*       __restrict__ out,         // [C,240,99]
                float*       __restrict__ centers_out, // [C]
                int C)
{
    const int t = threadIdx.x;

    __shared__ float s_d[NNB];
    __shared__ float s_inv[NNB];
    __shared__ float s_embi[NFEAT];
    __shared__ float s_embj[NNB * NFEAT]; // neighbor embeddings pre-scaled by 1/d
    __shared__ float s_norm[NNB * NNB];   // d_jk_norm, indexed q = j*16+k
    __shared__ float s_x[NNB], s_y[NNB], s_z[NNB];
    __shared__ int   s_tj[NNB];
    // double-buffered CTA-wide slab: 2 x 31680 B (parity carries across centers)
    __shared__ __align__(16) float s_stage[2][SLAB_FLOATS];

    const int warp = t >> 5;
    const int lane = t & 31;
    const int rot  = (lane - 3) & 31;
    const bool l0 = (lane == 0), l1 = (lane == 1), l2 = (lane == 2);
    const bool llt3 = (lane < 3);

    uint64_t policy;
    asm volatile("createpolicy.fractional.L2::evict_first.b64 %0, 1.0;"
                 : "=l"(policy));

    int it = 0;  // slab counter: s_stage parity carries across both centers

    #pragma unroll 1
    for (int cc = 0; cc < CPC; ++cc) {
        const int c = blockIdx.x * CPC + cc;   // two ADJACENT centers per CTA
        if (c >= C) break;

        // ---- prologue: register-chained gathers, one sync ----
        // (overlaps previous center's in-flight bulk stores)
        if (t < NNB) {
            float d = dist[c * NNB + t];
            int   a = j_idx[c * NNB + t];
            s_d[t]   = d;
            s_inv[t] = 1.0f / d;
            s_x[t]  = atoms_xyz[a * 3 + 0];
            s_y[t]  = atoms_xyz[a * 3 + 1];
            s_z[t]  = atoms_xyz[a * 3 + 2];
            s_tj[t] = types[a];
        } else if (t >= 32 && t < 64) {
            int ln = t - 32;
            int ai = i_idx[c];            // broadcast
            int ti = types[ai];           // broadcast
            s_embi[ln] = embed[ti * NFEAT + ln];
            if (ln == 0) centers_out[c] = (float)ai;
        }
        __syncthreads();

        // ---- tables: scaled neighbor embeddings + d_jk_norm ----
        for (int idx = t; idx < NNB * NFEAT; idx += 256) {
            int nb = idx >> 5;
            int f  = idx & 31;
            s_embj[idx] = embed[s_tj[nb] * NFEAT + f] * s_inv[nb];
        }
        {
            int j = t >> 4, k = t & 15;
            float dx = s_x[j] - s_x[k];
            float dy = s_y[j] - s_y[k];
            float dz = s_z[j] - s_z[k];
            float djk = sqrtf(dx * dx + dy * dy + dz * dz);
            float dj = s_d[j], dk = s_d[k];
            float mx = fmaxf(dj, dk), mn = fminf(dj, dk);
            s_norm[t] = (djk - mx + mn) / (2.0f * mn);
        }
        __syncthreads();

        const float embi_a = s_embi[rot];
        const float embi_b = s_embi[(29 + lane) < NFEAT ? (29 + lane) : 0];
        char* gbase = (char*)(out + (size_t)c * PER_C);

        // ---- build 80-pair slabs, drain each via ONE 31.7KB cp.async.bulk ----
        for (int s = 0; s < NSLABS; ++s, ++it) {
            float* buf = s_stage[it & 1];

            // Guard buffer reuse HERE (not after commit): the bulk read of this
            // buffer was committed 2 slabs ago and has had maximal time to
            // drain; commits flow out without stalling the CTA behind them.
            if (it >= 2) {
                if (t == 0)
                    asm volatile("cp.async.bulk.wait_group 1;" ::: "memory");
                __syncthreads();
            }

            #pragma unroll
            for (int r = 0; r < PPW; ++r) {
                const int rp = warp * PPW + r;       // row within slab
                const int p  = s * SLAB_PAIRS + rp;  // global pair index
                const int q  = p + (p >> 4) + 1;     // skip-diagonal flat index
                const int j  = q >> 4;
                const int k  = q & 15;

                const float dj  = s_d[j];
                const float dk  = s_d[k];
                const float njk = s_norm[q];
                const float ejv = s_embj[j * NFEAT + rot];
                const float ekv = s_embj[k * NFEAT + rot];

                float v0 = embi_a;               // [dj, dk, njk, emb_i[0..28]]
                if (l2) v0 = njk;
                if (l1) v0 = dk;
                if (l0) v0 = dj;
                float v1 = llt3 ? embi_b : ejv;  // [emb_i[29..31], e_j[0..28]]
                float v2 = llt3 ? ejv    : ekv;  // [e_j[29..31],  e_k[0..28]]

                float* rb = buf + rp * ROW;
                rb[lane]      = v0;
                rb[32 + lane] = v1;
                rb[64 + lane] = v2;
                if (llt3) rb[96 + lane] = ekv;   // e_k[29..31]
            }

            __syncthreads();   // slab fully built
            if (t == 0) {
                asm volatile("fence.proxy.async.shared::cta;" ::: "memory");
                uint32_t saddr = (uint32_t)__cvta_generic_to_shared(buf);
                asm volatile(
                    "cp.async.bulk.global.shared::cta.bulk_group.L2::cache_hint"
                    " [%0], [%1], %2, %3;"
                    :: "l"(gbase + (size_t)s * SLAB_BYTES), "r"(saddr),
                       "n"(SLAB_BYTES), "l"(policy)
                    : "memory");
                asm volatile("cp.async.bulk.commit_group;" ::: "memory");
            }
            // NOTE: no wait after commit — next iteration's pre-build guard
            // (or the exit drain) provides the ordering.
        }
        // no full drain between the two centers — pipeline carries over
    }

    // SMEM handed to next CTA on this SM: drain fully before exit
    __syncthreads();
    if (t == 0)
        asm volatile("cp.async.bulk.wait_group 0;" ::: "memory");
}

extern "C" void kernel_launch(void* const* d_in, const int* in_sizes, int n_in,
                              void* d_out, int out_size)
{
    const float* atoms_xyz = (const float*)d_in[0];
    const float* embed     = (const float*)d_in[1];
    const float* dist      = (const float*)d_in[2];
    const int*   types     = (const int*)  d_in[3];
    const int*   i_idx     = (const int*)  d_in[4];
    const int*   j_idx     = (const int*)  d_in[5];

    const int C = in_sizes[4];                 // number of centers
    float* out = (float*)d_out;
    float* centers_out = out + (size_t)C * PER_C;

    int grid = (C + CPC - 1) / CPC;            // 2 adjacent centers per CTA

    ang_desc_kernel<<<grid, 256>>>(atoms_xyz, embed, dist, types,
                                   i_idx, j_idx, out, centers_out, C);
}